// round 6
// baseline (speedup 1.0000x reference)
#include <cuda_runtime.h>
#include <cuda_fp16.h>
#include <cstdint>

#define BATCH 8
#define NN 2048
#define FD 256
#define EPSV 1e-7f
#define NSLOPE 0.2f

// ---------------- device scratch ----------------
static __device__ float g_Wh[BATCH * NN * FD];                 // 16 MB
static __device__ float g_P [BATCH * NN];
static __device__ float g_Q [BATCH * NN];
static __device__ float g_E1[BATCH * NN];
static __device__ float g_E2[BATCH * NN];
static __device__ float g_F1[BATCH * NN];
static __device__ float g_F2[BATCH * NN];
static __device__ float g_D [BATCH * NN];
static __device__ __half g_M1[(size_t)BATCH * NN * NN];        // 64 MB pos-mask
static __device__ __half g_M2[(size_t)BATCH * NN * NN];        // 64 MB neg-mask
static __device__ __half g_H1[BATCH * NN * FD];                // (F1/D)*Wh fp16
static __device__ __half g_H2[BATCH * NN * FD];                // (F2/D)*Wh fp16

// ---------------- helpers ----------------
__device__ __forceinline__ unsigned long long pack2(float x, float y) {
    unsigned long long r;
    asm("mov.b64 %0, {%1, %2};" : "=l"(r) : "f"(x), "f"(y));
    return r;
}
__device__ __forceinline__ float2 unpack2(unsigned long long v) {
    float2 r;
    asm("mov.b64 {%0, %1}, %2;" : "=f"(r.x), "=f"(r.y) : "l"(v));
    return r;
}
__device__ __forceinline__ void ffma2(unsigned long long& d,
                                      unsigned long long a,
                                      unsigned long long b) {
    asm("fma.rn.f32x2 %0, %1, %2, %3;" : "=l"(d) : "l"(a), "l"(b), "l"(d));
}
__device__ __forceinline__ uint32_t smem_u32(const void* p) {
    uint32_t a;
    asm("{ .reg .u64 t; cvta.to.shared.u64 t, %1; cvt.u32.u64 %0, t; }" : "=r"(a) : "l"(p));
    return a;
}
__device__ __forceinline__ void cp_async16(uint32_t dst, const void* src) {
    asm volatile("cp.async.cg.shared.global [%0], [%1], 16;" :: "r"(dst), "l"(src));
}
#define CP_COMMIT() asm volatile("cp.async.commit_group;" ::: "memory")

__device__ __forceinline__ void ldsm_x4(uint32_t& r0, uint32_t& r1, uint32_t& r2,
                                        uint32_t& r3, uint32_t addr) {
    asm volatile("ldmatrix.sync.aligned.m8n8.x4.shared.b16 {%0,%1,%2,%3}, [%4];"
                 : "=r"(r0), "=r"(r1), "=r"(r2), "=r"(r3) : "r"(addr));
}
__device__ __forceinline__ void ldsm_x4_t(uint32_t& r0, uint32_t& r1, uint32_t& r2,
                                          uint32_t& r3, uint32_t addr) {
    asm volatile("ldmatrix.sync.aligned.m8n8.x4.trans.shared.b16 {%0,%1,%2,%3}, [%4];"
                 : "=r"(r0), "=r"(r1), "=r"(r2), "=r"(r3) : "r"(addr));
}
__device__ __forceinline__ void mma16816(float* d, const uint32_t* a, uint32_t b0,
                                         uint32_t b1) {
    asm volatile("mma.sync.aligned.m16n8k16.row.col.f32.f16.f16.f32 "
                 "{%0,%1,%2,%3}, {%4,%5,%6,%7}, {%8,%9}, {%0,%1,%2,%3};"
                 : "+f"(d[0]), "+f"(d[1]), "+f"(d[2]), "+f"(d[3])
                 : "r"(a[0]), "r"(a[1]), "r"(a[2]), "r"(a[3]), "r"(b0), "r"(b1));
}

// =====================================================================
// K1: Wh = x @ W (fp32 f32x2) + FUSED attention-vector epilogue
// =====================================================================
__global__ __launch_bounds__(256) void k_gemm_wh(const float* __restrict__ x,
                                                 const float* __restrict__ W,
                                                 const float* __restrict__ aw,
                                                 const float* __restrict__ ab) {
    __shared__ __align__(16) float Xs[64][32];
    __shared__ __align__(16) float Ws[32][256];
    const int r0 = blockIdx.x * 64;
    const int tid = threadIdx.x, lane = tid & 31, w = tid >> 5;

    unsigned long long acc[8][4];
#pragma unroll
    for (int r = 0; r < 8; r++)
#pragma unroll
        for (int m = 0; m < 4; m++) acc[r][m] = 0ull;

    for (int k0 = 0; k0 < FD; k0 += 32) {
#pragma unroll
        for (int rr = 0; rr < 8; rr++) {
            int e = tid + 256 * rr;
            Xs[e >> 5][e & 31] = x[(r0 + (e >> 5)) * FD + k0 + (e & 31)];
        }
#pragma unroll
        for (int rr = 0; rr < 8; rr++) {
            int e = tid + 256 * rr;
            int j = e >> 6, o4 = e & 63;
            *(float4*)&Ws[j][o4 * 4] = *(const float4*)&W[(k0 + j) * FD + o4 * 4];
        }
        __syncthreads();
#pragma unroll 4
        for (int kk = 0; kk < 32; kk++) {
            unsigned long long cb[8];
#pragma unroll
            for (int r = 0; r < 8; r++) { float c = Xs[8 * w + r][kk]; cb[r] = pack2(c, c); }
            unsigned long long wv[4];
#pragma unroll
            for (int m = 0; m < 4; m++)
                wv[m] = *(const unsigned long long*)&Ws[kk][2 * lane + 64 * m];
#pragma unroll
            for (int r = 0; r < 8; r++)
#pragma unroll
                for (int m = 0; m < 4; m++) ffma2(acc[r][m], cb[r], wv[m]);
        }
        __syncthreads();
    }

    float2 a1v[4], a2v[4];
#pragma unroll
    for (int m = 0; m < 4; m++) {
        a1v[m] = *(const float2*)&aw[2 * lane + 64 * m];
        a2v[m] = *(const float2*)&aw[FD + 2 * lane + 64 * m];
    }
#pragma unroll
    for (int r = 0; r < 8; r++) {
        float s1 = 0.f, s2 = 0.f;
#pragma unroll
        for (int m = 0; m < 4; m++) {
            float2 v = unpack2(acc[r][m]);
            *(float2*)&g_Wh[(r0 + 8 * w + r) * FD + 2 * lane + 64 * m] = v;
            s1 += v.x * a1v[m].x + v.y * a1v[m].y;
            s2 += v.x * a2v[m].x + v.y * a2v[m].y;
        }
#pragma unroll
        for (int off = 16; off > 0; off >>= 1) {
            s1 += __shfl_xor_sync(0xffffffffu, s1, off);
            s2 += __shfl_xor_sync(0xffffffffu, s2, off);
        }
        if (lane == 0) {
            int row = r0 + 8 * w + r;
            float P = s1, Q = s2 + ab[0];
            g_P[row] = P; g_Q[row] = Q;
            g_E1[row] = expf(P);          g_E2[row] = expf(NSLOPE * P);
            g_F1[row] = expf(Q);          g_F2[row] = expf(NSLOPE * Q);
            g_D[row] = 0.f;
        }
    }
}

// =====================================================================
// K3: column sums D[b,j] + fp16 masks; 2 columns per thread
// grid: (NN/512, BATCH, NN/256), 256 threads
// =====================================================================
__global__ __launch_bounds__(256) void k_colsum(const float* __restrict__ A) {
    const int b = blockIdx.y;
    const int j0 = blockIdx.x * 512 + threadIdx.x * 2;
    const int ibase = blockIdx.z * 256;
    __shared__ float sP[256], sE1[256], sE2[256];
    sP [threadIdx.x] = g_P [b * NN + ibase + threadIdx.x];
    sE1[threadIdx.x] = g_E1[b * NN + ibase + threadIdx.x];
    sE2[threadIdx.x] = g_E2[b * NN + ibase + threadIdx.x];
    __syncthreads();
    const float Qa = g_Q[b * NN + j0],     F1a = g_F1[b * NN + j0],
                F2a = g_F2[b * NN + j0];
    const float Qb = g_Q[b * NN + j0 + 1], F1b = g_F1[b * NN + j0 + 1],
                F2b = g_F2[b * NN + j0 + 1];
    const float* Ab = A + (size_t)(b * NN + ibase) * NN + j0;
    float acc0 = 0.f, acc1 = 0.f;
#pragma unroll 4
    for (int ii = 0; ii < 256; ii++) {
        float2 a = __ldcs((const float2*)(Ab + (size_t)ii * NN));
        float p = sP[ii], e1 = sE1[ii], e2 = sE2[ii];
        bool pos0 = (p + Qa > 0.f);
        bool pos1 = (p + Qb > 0.f);
        acc0 = fmaf(a.x, pos0 ? e1 * F1a : e2 * F2a, acc0);
        acc1 = fmaf(a.y, pos1 ? e1 * F1b : e2 * F2b, acc1);
        size_t mi = (size_t)(b * NN + ibase + ii) * NN + j0;
        __half2 m1 = __floats2half2_rn(pos0 ? a.x : 0.f, pos1 ? a.y : 0.f);
        __half2 m2 = __floats2half2_rn(pos0 ? 0.f : a.x, pos1 ? 0.f : a.y);
        __stcs((__half2*)&g_M1[mi], m1);
        __stcs((__half2*)&g_M2[mi], m2);
    }
    atomicAdd(&g_D[b * NN + j0], acc0);
    atomicAdd(&g_D[b * NN + j0 + 1], acc1);
}

// =====================================================================
// K_hprep: H1 = (F1/D)*Wh, H2 = (F2/D)*Wh in fp16
// =====================================================================
__global__ __launch_bounds__(256) void k_hprep() {
    int e4 = blockIdx.x * 256 + threadIdx.x;
    int row = e4 >> 6;
    float inv = 1.f / (g_D[row] + EPSV);
    float r1 = g_F1[row] * inv, r2 = g_F2[row] * inv;
    float4 w = ((const float4*)g_Wh)[e4];
    __half2* h1 = (__half2*)g_H1;
    __half2* h2 = (__half2*)g_H2;
    h1[e4 * 2]     = __floats2half2_rn(w.x * r1, w.y * r1);
    h1[e4 * 2 + 1] = __floats2half2_rn(w.z * r1, w.w * r1);
    h2[e4 * 2]     = __floats2half2_rn(w.x * r2, w.y * r2);
    h2[e4 * 2 + 1] = __floats2half2_rn(w.z * r2, w.w * r2);
}

// =====================================================================
// K4: HMMA mask-GEMM, 512 threads, warp tile 32i x 16o, 2 CTAs/SM target.
// Block 128i x 64o; stage = 32 j; 4-stage cp.async pipeline (96 KB).
// Stage SMEM (24576B): M1 8K | M2 8K | B1 4K | B2 4K.
// =====================================================================
#define STG_STRIDE 24576

__device__ __forceinline__ uint32_t m_off(int i, int cq) {
    return (uint32_t)(((i >> 1) << 7) + (((((i & 1) << 2) | cq) ^ ((i >> 1) & 7)) << 4));
}
__device__ __forceinline__ uint32_t b_off(int j, int oc) {
    return (uint32_t)((j << 7) + (((oc ^ (j & 7))) << 4));
}

__global__ void __launch_bounds__(512, 2) k_mma(float* __restrict__ out) {
    extern __shared__ __align__(128) char smem[];
    const uint32_t sb = smem_u32(smem);
    const int tid = threadIdx.x, lane = tid & 31, wid = tid >> 5;
    const int b = blockIdx.z;
    const int i0 = blockIdx.x * 128;
    const int o0 = blockIdx.y * 64;
    const int isub = (wid & 3) * 32;        // warp's 32-i subtile
    const int ow   = wid >> 2;              // warp's 16-o subtile (0..3)
    const int ocb  = ow * 2;                // o-chunk base (chunks of 8)

    float acc[2][2][2][4];
#pragma unroll
    for (int t = 0; t < 2; t++)
#pragma unroll
        for (int m = 0; m < 2; m++)
#pragma unroll
            for (int n = 0; n < 2; n++)
#pragma unroll
                for (int k = 0; k < 4; k++) acc[t][m][n][k] = 0.f;

    auto issue = [&](int t) {
        const int j0 = t * 32;
        uint32_t stg = sb + (t & 3) * STG_STRIDE;
#pragma unroll
        for (int r = 0; r < 2; r++) {
            int idx = tid + 512 * r;
            int tens = idx >> 9, rem = idx & 511;
            int i = rem >> 2, cq = rem & 3;
            const __half* src = (tens ? g_M2 : g_M1) +
                ((size_t)(b * NN + i0 + i) * NN + j0 + cq * 8);
            cp_async16(stg + tens * 8192 + m_off(i, cq), src);
        }
        {
            int tens = tid >> 8, rem = tid & 255;
            int j = rem >> 3, oc = rem & 7;
            const __half* src = (tens ? g_H2 : g_H1) +
                ((size_t)(b * NN + j0 + j) * FD + o0 + oc * 8);
            cp_async16(stg + 16384 + tens * 4096 + b_off(j, oc), src);
        }
        CP_COMMIT();
    };

    issue(0); issue(1); issue(2);

    const int jhalf = (lane >> 4) & 1, oblk = (lane >> 3) & 1;
    const int q = lane >> 3;

    for (int t = 0; t < 64; t++) {
        if (t <= 61)      { asm volatile("cp.async.wait_group 2;" ::: "memory"); }
        else if (t == 62) { asm volatile("cp.async.wait_group 1;" ::: "memory"); }
        else              { asm volatile("cp.async.wait_group 0;" ::: "memory"); }
        __syncthreads();

        uint32_t stg = sb + (t & 3) * STG_STRIDE;
#pragma unroll
        for (int tens = 0; tens < 2; tens++) {
            // B fragments: one ldsm_x4_t per kt covers 16j x 16o
            uint32_t Bf[2][4];
            uint32_t bb = stg + 16384 + tens * 4096;
#pragma unroll
            for (int kt = 0; kt < 2; kt++) {
                int j = kt * 16 + jhalf * 8 + (lane & 7);
                ldsm_x4_t(Bf[kt][0], Bf[kt][1], Bf[kt][2], Bf[kt][3],
                          bb + b_off(j, ocb + oblk));
            }
            uint32_t mb = stg + tens * 8192;
#pragma unroll
            for (int m = 0; m < 2; m++) {
#pragma unroll
                for (int kt = 0; kt < 2; kt++) {
                    int i = isub + m * 16 + ((q & 1) << 3) + (lane & 7);
                    int cq = (kt << 1) + (q >> 1);
                    uint32_t a[4];
                    ldsm_x4(a[0], a[1], a[2], a[3], mb + m_off(i, cq));
                    mma16816(acc[tens][m][0], a, Bf[kt][0], Bf[kt][2]);
                    mma16816(acc[tens][m][1], a, Bf[kt][1], Bf[kt][3]);
                }
            }
        }
        if (t + 3 < 64) issue(t + 3);
    }

    // ---- epilogue: out = E1*D1 + E2*D2 ----
    const int gid = lane >> 2, t4 = lane & 3;
#pragma unroll
    for (int m = 0; m < 2; m++) {
        int r0 = i0 + isub + m * 16 + gid;
        int r1 = r0 + 8;
        float e1a = g_E1[b * NN + r0], e2a = g_E2[b * NN + r0];
        float e1b = g_E1[b * NN + r1], e2b = g_E2[b * NN + r1];
#pragma unroll
        for (int nt = 0; nt < 2; nt++) {
            int o = o0 + ow * 16 + nt * 8 + 2 * t4;
            float2 v0, v1;
            v0.x = e1a * acc[0][m][nt][0] + e2a * acc[1][m][nt][0];
            v0.y = e1a * acc[0][m][nt][1] + e2a * acc[1][m][nt][1];
            v1.x = e1b * acc[0][m][nt][2] + e2b * acc[1][m][nt][2];
            v1.y = e1b * acc[0][m][nt][3] + e2b * acc[1][m][nt][3];
            *(float2*)&out[(size_t)(b * NN + r0) * FD + o] = v0;
            *(float2*)&out[(size_t)(b * NN + r1) * FD + o] = v1;
        }
    }
}

// =====================================================================
extern "C" void kernel_launch(void* const* d_in, const int* in_sizes, int n_in,
                              void* d_out, int out_size) {
    (void)in_sizes; (void)n_in; (void)out_size;
    const float* A  = (const float*)d_in[0];
    const float* x  = (const float*)d_in[1];
    const float* W  = (const float*)d_in[2];
    const float* aw = (const float*)d_in[3];
    const float* ab = (const float*)d_in[4];
    float* out = (float*)d_out;

    cudaFuncSetAttribute(k_mma, cudaFuncAttributeMaxDynamicSharedMemorySize,
                         4 * STG_STRIDE);

    k_gemm_wh<<<(BATCH * NN) / 64, 256>>>(x, W, aw, ab);
    k_colsum<<<dim3(NN / 512, BATCH, NN / 256), 256>>>(A);
    k_hprep<<<(BATCH * NN * FD) / 1024, 256>>>();
    k_mma<<<dim3(NN / 128, FD / 64, BATCH), 512, 4 * STG_STRIDE>>>(out);
}

// round 7
// speedup vs baseline: 1.3152x; 1.3152x over previous
#include <cuda_runtime.h>
#include <cuda_fp16.h>
#include <cstdint>

#define BATCH 8
#define NN 2048
#define FD 256
#define EPSV 1e-7f
#define NSLOPE 0.2f

// ---------------- device scratch ----------------
static __device__ float g_Wh[BATCH * NN * FD];                 // 16 MB
static __device__ float g_P [BATCH * NN];
static __device__ float g_Q [BATCH * NN];
static __device__ float g_E1[BATCH * NN];
static __device__ float g_E2[BATCH * NN];
static __device__ float g_F1[BATCH * NN];
static __device__ float g_F2[BATCH * NN];
static __device__ float g_D [BATCH * NN];
static __device__ __half g_M1[(size_t)BATCH * NN * NN];        // 64 MB E1-folded pos-mask
static __device__ __half g_M2[(size_t)BATCH * NN * NN];        // 64 MB E2-folded neg-mask
static __device__ __half g_H1[BATCH * NN * FD];                // (F1/D)*Wh fp16
static __device__ __half g_H2[BATCH * NN * FD];                // (F2/D)*Wh fp16

// ---------------- helpers ----------------
__device__ __forceinline__ unsigned long long pack2(float x, float y) {
    unsigned long long r;
    asm("mov.b64 %0, {%1, %2};" : "=l"(r) : "f"(x), "f"(y));
    return r;
}
__device__ __forceinline__ float2 unpack2(unsigned long long v) {
    float2 r;
    asm("mov.b64 {%0, %1}, %2;" : "=f"(r.x), "=f"(r.y) : "l"(v));
    return r;
}
__device__ __forceinline__ void ffma2(unsigned long long& d,
                                      unsigned long long a,
                                      unsigned long long b) {
    asm("fma.rn.f32x2 %0, %1, %2, %3;" : "=l"(d) : "l"(a), "l"(b), "l"(d));
}
__device__ __forceinline__ uint32_t smem_u32(const void* p) {
    uint32_t a;
    asm("{ .reg .u64 t; cvta.to.shared.u64 t, %1; cvt.u32.u64 %0, t; }" : "=r"(a) : "l"(p));
    return a;
}
__device__ __forceinline__ void cp_async16(uint32_t dst, const void* src) {
    asm volatile("cp.async.cg.shared.global [%0], [%1], 16;" :: "r"(dst), "l"(src));
}
#define CP_COMMIT() asm volatile("cp.async.commit_group;" ::: "memory")

__device__ __forceinline__ void ldsm_x4(uint32_t& r0, uint32_t& r1, uint32_t& r2,
                                        uint32_t& r3, uint32_t addr) {
    asm volatile("ldmatrix.sync.aligned.m8n8.x4.shared.b16 {%0,%1,%2,%3}, [%4];"
                 : "=r"(r0), "=r"(r1), "=r"(r2), "=r"(r3) : "r"(addr));
}
__device__ __forceinline__ void ldsm_x4_t(uint32_t& r0, uint32_t& r1, uint32_t& r2,
                                          uint32_t& r3, uint32_t addr) {
    asm volatile("ldmatrix.sync.aligned.m8n8.x4.trans.shared.b16 {%0,%1,%2,%3}, [%4];"
                 : "=r"(r0), "=r"(r1), "=r"(r2), "=r"(r3) : "r"(addr));
}
__device__ __forceinline__ void mma16816(float* d, const uint32_t* a, uint32_t b0,
                                         uint32_t b1) {
    asm volatile("mma.sync.aligned.m16n8k16.row.col.f32.f16.f16.f32 "
                 "{%0,%1,%2,%3}, {%4,%5,%6,%7}, {%8,%9}, {%0,%1,%2,%3};"
                 : "+f"(d[0]), "+f"(d[1]), "+f"(d[2]), "+f"(d[3])
                 : "r"(a[0]), "r"(a[1]), "r"(a[2]), "r"(a[3]), "r"(b0), "r"(b1));
}

// =====================================================================
// K1: Wh = x @ W (fp32 f32x2) + FUSED attention-vector epilogue
// =====================================================================
__global__ __launch_bounds__(256) void k_gemm_wh(const float* __restrict__ x,
                                                 const float* __restrict__ W,
                                                 const float* __restrict__ aw,
                                                 const float* __restrict__ ab) {
    __shared__ __align__(16) float Xs[64][32];
    __shared__ __align__(16) float Ws[32][256];
    const int r0 = blockIdx.x * 64;
    const int tid = threadIdx.x, lane = tid & 31, w = tid >> 5;

    unsigned long long acc[8][4];
#pragma unroll
    for (int r = 0; r < 8; r++)
#pragma unroll
        for (int m = 0; m < 4; m++) acc[r][m] = 0ull;

    for (int k0 = 0; k0 < FD; k0 += 32) {
#pragma unroll
        for (int rr = 0; rr < 8; rr++) {
            int e = tid + 256 * rr;
            Xs[e >> 5][e & 31] = x[(r0 + (e >> 5)) * FD + k0 + (e & 31)];
        }
#pragma unroll
        for (int rr = 0; rr < 8; rr++) {
            int e = tid + 256 * rr;
            int j = e >> 6, o4 = e & 63;
            *(float4*)&Ws[j][o4 * 4] = *(const float4*)&W[(k0 + j) * FD + o4 * 4];
        }
        __syncthreads();
#pragma unroll 4
        for (int kk = 0; kk < 32; kk++) {
            unsigned long long cb[8];
#pragma unroll
            for (int r = 0; r < 8; r++) { float c = Xs[8 * w + r][kk]; cb[r] = pack2(c, c); }
            unsigned long long wv[4];
#pragma unroll
            for (int m = 0; m < 4; m++)
                wv[m] = *(const unsigned long long*)&Ws[kk][2 * lane + 64 * m];
#pragma unroll
            for (int r = 0; r < 8; r++)
#pragma unroll
                for (int m = 0; m < 4; m++) ffma2(acc[r][m], cb[r], wv[m]);
        }
        __syncthreads();
    }

    float2 a1v[4], a2v[4];
#pragma unroll
    for (int m = 0; m < 4; m++) {
        a1v[m] = *(const float2*)&aw[2 * lane + 64 * m];
        a2v[m] = *(const float2*)&aw[FD + 2 * lane + 64 * m];
    }
#pragma unroll
    for (int r = 0; r < 8; r++) {
        float s1 = 0.f, s2 = 0.f;
#pragma unroll
        for (int m = 0; m < 4; m++) {
            float2 v = unpack2(acc[r][m]);
            *(float2*)&g_Wh[(r0 + 8 * w + r) * FD + 2 * lane + 64 * m] = v;
            s1 += v.x * a1v[m].x + v.y * a1v[m].y;
            s2 += v.x * a2v[m].x + v.y * a2v[m].y;
        }
#pragma unroll
        for (int off = 16; off > 0; off >>= 1) {
            s1 += __shfl_xor_sync(0xffffffffu, s1, off);
            s2 += __shfl_xor_sync(0xffffffffu, s2, off);
        }
        if (lane == 0) {
            int row = r0 + 8 * w + r;
            float P = s1, Q = s2 + ab[0];
            g_P[row] = P; g_Q[row] = Q;
            g_E1[row] = expf(P);          g_E2[row] = expf(NSLOPE * P);
            g_F1[row] = expf(Q);          g_F2[row] = expf(NSLOPE * Q);
            g_D[row] = 0.f;
        }
    }
}

// =====================================================================
// K3: column sums D[b,j] + E-folded fp16 masks (R5-proven store pattern)
// =====================================================================
__global__ __launch_bounds__(256) void k_colsum(const float* __restrict__ A) {
    const int b = blockIdx.y;
    const int j = blockIdx.x * 256 + threadIdx.x;
    const int ibase = blockIdx.z * 256;
    __shared__ float sP[256], sE1[256], sE2[256];
    __shared__ __half sH1[256], sH2[256];
    {
        float e1 = g_E1[b * NN + ibase + threadIdx.x];
        float e2 = g_E2[b * NN + ibase + threadIdx.x];
        sP [threadIdx.x] = g_P[b * NN + ibase + threadIdx.x];
        sE1[threadIdx.x] = e1;  sE2[threadIdx.x] = e2;
        sH1[threadIdx.x] = __float2half_rn(e1);
        sH2[threadIdx.x] = __float2half_rn(e2);
    }
    __syncthreads();
    const float Qj = g_Q[b * NN + j], F1j = g_F1[b * NN + j], F2j = g_F2[b * NN + j];
    const float* Ab = A + (size_t)(b * NN + ibase) * NN + j;
    const __half hz = __ushort_as_half(0);
    float acc = 0.f;
#pragma unroll 4
    for (int ii = 0; ii < 256; ii++) {
        float a = Ab[(size_t)ii * NN];
        bool pos = (sP[ii] + Qj > 0.f);
        bool nz = (a != 0.f);
        acc = fmaf(a, pos ? sE1[ii] * F1j : sE2[ii] * F2j, acc);
        size_t mi = (size_t)(b * NN + ibase + ii) * NN + j;
        g_M1[mi] = (nz && pos)  ? sH1[ii] : hz;
        g_M2[mi] = (nz && !pos) ? sH2[ii] : hz;
    }
    atomicAdd(&g_D[b * NN + j], acc);
}

// =====================================================================
// K_hprep: H1 = (F1/D)*Wh, H2 = (F2/D)*Wh in fp16
// =====================================================================
__global__ __launch_bounds__(256) void k_hprep() {
    int e4 = blockIdx.x * 256 + threadIdx.x;
    int row = e4 >> 6;
    float inv = 1.f / (g_D[row] + EPSV);
    float r1 = g_F1[row] * inv, r2 = g_F2[row] * inv;
    float4 w = ((const float4*)g_Wh)[e4];
    __half2* h1 = (__half2*)g_H1;
    __half2* h2 = (__half2*)g_H2;
    h1[e4 * 2]     = __floats2half2_rn(w.x * r1, w.y * r1);
    h1[e4 * 2 + 1] = __floats2half2_rn(w.z * r1, w.w * r1);
    h2[e4 * 2]     = __floats2half2_rn(w.x * r2, w.y * r2);
    h2[e4 * 2 + 1] = __floats2half2_rn(w.z * r2, w.w * r2);
}

// =====================================================================
// K4: HMMA mask-GEMM, E-folded single accumulator.
// Block 128i x 64o, 256 threads, warp tile 32i x 32o (LDS-optimal).
// 3-stage cp.async pipeline (72 KB SMEM) -> 3 CTAs/SM.
// Stage SMEM (24576B): M1 8K | M2 8K | B1 4K | B2 4K.
// out[b,i,:] = M1'@H1 + M2'@H2   (E already folded into masks)
// =====================================================================
#define STG_STRIDE 24576
#define NSTAGE 3

__device__ __forceinline__ uint32_t m_off(int i, int cq) {
    return (uint32_t)(((i >> 1) << 7) + (((((i & 1) << 2) | cq) ^ ((i >> 1) & 7)) << 4));
}
__device__ __forceinline__ uint32_t b_off(int j, int oc) {
    return (uint32_t)((j << 7) + (((oc ^ (j & 7))) << 4));
}

__global__ void __launch_bounds__(256, 3) k_mma(float* __restrict__ out) {
    extern __shared__ __align__(128) char smem[];
    const uint32_t sb = smem_u32(smem);
    const int tid = threadIdx.x, lane = tid & 31, wid = tid >> 5;
    const int b = blockIdx.z;
    const int i0 = blockIdx.x * 128;
    const int o0 = blockIdx.y * 64;
    const int isub = (wid & 3) * 32;
    const int ocb = (wid >> 2) * 4;

    float acc[2][4][4];
#pragma unroll
    for (int m = 0; m < 2; m++)
#pragma unroll
        for (int n = 0; n < 4; n++)
#pragma unroll
            for (int k = 0; k < 4; k++) acc[m][n][k] = 0.f;

    auto issue = [&](int t) {
        const int j0 = t * 32;
        uint32_t stg = sb + (t % NSTAGE) * STG_STRIDE;
#pragma unroll
        for (int r = 0; r < 4; r++) {
            int idx = tid + 256 * r;
            int tens = idx >> 9, rem = idx & 511;
            int i = rem >> 2, cq = rem & 3;
            const __half* src = (tens ? g_M2 : g_M1) +
                ((size_t)(b * NN + i0 + i) * NN + j0 + cq * 8);
            cp_async16(stg + tens * 8192 + m_off(i, cq), src);
        }
#pragma unroll
        for (int r = 0; r < 2; r++) {
            int idx = tid + 256 * r;
            int tens = idx >> 8, rem = idx & 255;
            int j = rem >> 3, oc = rem & 7;
            const __half* src = (tens ? g_H2 : g_H1) +
                ((size_t)(b * NN + j0 + j) * FD + o0 + oc * 8);
            cp_async16(stg + 16384 + tens * 4096 + b_off(j, oc), src);
        }
        CP_COMMIT();
    };

    issue(0); issue(1);

    for (int t = 0; t < 64; t++) {
        if (t < 63) { asm volatile("cp.async.wait_group 1;" ::: "memory"); }
        else        { asm volatile("cp.async.wait_group 0;" ::: "memory"); }
        __syncthreads();

        uint32_t stg = sb + (t % NSTAGE) * STG_STRIDE;
#pragma unroll
        for (int tens = 0; tens < 2; tens++) {
            uint32_t Bf[4][4];
            uint32_t bb = stg + 16384 + tens * 4096;
#pragma unroll
            for (int jb = 0; jb < 4; jb++) {
                int oblk = lane >> 3;
                int j = jb * 8 + (lane & 7);
                uint32_t addr = bb + b_off(j, ocb + oblk);
                ldsm_x4_t(Bf[jb][0], Bf[jb][1], Bf[jb][2], Bf[jb][3], addr);
            }
            uint32_t mb = stg + tens * 8192;
#pragma unroll
            for (int m = 0; m < 2; m++) {
#pragma unroll
                for (int kt = 0; kt < 2; kt++) {
                    int q = lane >> 3;
                    int i = isub + m * 16 + ((q & 1) << 3) + (lane & 7);
                    int cq = (kt << 1) + (q >> 1);
                    uint32_t a[4];
                    ldsm_x4(a[0], a[1], a[2], a[3], mb + m_off(i, cq));
#pragma unroll
                    for (int nt = 0; nt < 4; nt++)
                        mma16816(acc[m][nt], a, Bf[2 * kt][nt], Bf[2 * kt + 1][nt]);
                }
            }
        }
        if (t + 2 < 64) issue(t + 2);
    }

    // ---- epilogue: direct store (E already folded) ----
    const int gid = lane >> 2, t4 = lane & 3;
#pragma unroll
    for (int m = 0; m < 2; m++) {
        int r0 = i0 + isub + m * 16 + gid;
        int r1 = r0 + 8;
#pragma unroll
        for (int nt = 0; nt < 4; nt++) {
            int o = o0 + ocb * 8 + nt * 8 + 2 * t4;
            float2 v0, v1;
            v0.x = acc[m][nt][0]; v0.y = acc[m][nt][1];
            v1.x = acc[m][nt][2]; v1.y = acc[m][nt][3];
            *(float2*)&out[(size_t)(b * NN + r0) * FD + o] = v0;
            *(float2*)&out[(size_t)(b * NN + r1) * FD + o] = v1;
        }
    }
}

// =====================================================================
extern "C" void kernel_launch(void* const* d_in, const int* in_sizes, int n_in,
                              void* d_out, int out_size) {
    (void)in_sizes; (void)n_in; (void)out_size;
    const float* A  = (const float*)d_in[0];
    const float* x  = (const float*)d_in[1];
    const float* W  = (const float*)d_in[2];
    const float* aw = (const float*)d_in[3];
    const float* ab = (const float*)d_in[4];
    float* out = (float*)d_out;

    cudaFuncSetAttribute(k_mma, cudaFuncAttributeMaxDynamicSharedMemorySize,
                         NSTAGE * STG_STRIDE);

    k_gemm_wh<<<(BATCH * NN) / 64, 256>>>(x, W, aw, ab);
    k_colsum<<<dim3(NN / 256, BATCH, NN / 256), 256>>>(A);
    k_hprep<<<(BATCH * NN * FD) / 1024, 256>>>();
    k_mma<<<dim3(NN / 128, FD / 64, BATCH), 256, NSTAGE * STG_STRIDE>>>(out);
}

// round 8
// speedup vs baseline: 1.3166x; 1.0010x over previous
#include <cuda_runtime.h>
#include <cuda_fp16.h>
#include <cstdint>

#define BATCH 8
#define NN 2048
#define FD 256
#define EPSV 1e-7f
#define NSLOPE 0.2f

// ---------------- device scratch ----------------
static __device__ float g_Wh[BATCH * NN * FD];                 // 16 MB
static __device__ float g_P [BATCH * NN];
static __device__ float g_Q [BATCH * NN];
static __device__ float g_E1[BATCH * NN];
static __device__ float g_E2[BATCH * NN];
static __device__ float g_F1[BATCH * NN];
static __device__ float g_F2[BATCH * NN];
static __device__ float g_D [BATCH * NN];
static __device__ __half g_M1[(size_t)BATCH * NN * NN];        // 64 MB E1-folded pos-mask
static __device__ __half g_M2[(size_t)BATCH * NN * NN];        // 64 MB E2-folded neg-mask
static __device__ __half g_H1[BATCH * NN * FD];                // (F1/D)*Wh fp16
static __device__ __half g_H2[BATCH * NN * FD];                // (F2/D)*Wh fp16

// ---------------- helpers ----------------
__device__ __forceinline__ unsigned long long pack2(float x, float y) {
    unsigned long long r;
    asm("mov.b64 %0, {%1, %2};" : "=l"(r) : "f"(x), "f"(y));
    return r;
}
__device__ __forceinline__ float2 unpack2(unsigned long long v) {
    float2 r;
    asm("mov.b64 {%0, %1}, %2;" : "=f"(r.x), "=f"(r.y) : "l"(v));
    return r;
}
__device__ __forceinline__ void ffma2(unsigned long long& d,
                                      unsigned long long a,
                                      unsigned long long b) {
    asm("fma.rn.f32x2 %0, %1, %2, %3;" : "=l"(d) : "l"(a), "l"(b), "l"(d));
}
__device__ __forceinline__ uint32_t smem_u32(const void* p) {
    uint32_t a;
    asm("{ .reg .u64 t; cvta.to.shared.u64 t, %1; cvt.u32.u64 %0, t; }" : "=r"(a) : "l"(p));
    return a;
}
__device__ __forceinline__ void cp_async16(uint32_t dst, const void* src) {
    asm volatile("cp.async.cg.shared.global [%0], [%1], 16;" :: "r"(dst), "l"(src));
}
#define CP_COMMIT() asm volatile("cp.async.commit_group;" ::: "memory")

__device__ __forceinline__ void ldsm_x4(uint32_t& r0, uint32_t& r1, uint32_t& r2,
                                        uint32_t& r3, uint32_t addr) {
    asm volatile("ldmatrix.sync.aligned.m8n8.x4.shared.b16 {%0,%1,%2,%3}, [%4];"
                 : "=r"(r0), "=r"(r1), "=r"(r2), "=r"(r3) : "r"(addr));
}
__device__ __forceinline__ void ldsm_x4_t(uint32_t& r0, uint32_t& r1, uint32_t& r2,
                                          uint32_t& r3, uint32_t addr) {
    asm volatile("ldmatrix.sync.aligned.m8n8.x4.trans.shared.b16 {%0,%1,%2,%3}, [%4];"
                 : "=r"(r0), "=r"(r1), "=r"(r2), "=r"(r3) : "r"(addr));
}
__device__ __forceinline__ void mma16816(float* d, const uint32_t* a, uint32_t b0,
                                         uint32_t b1) {
    asm volatile("mma.sync.aligned.m16n8k16.row.col.f32.f16.f16.f32 "
                 "{%0,%1,%2,%3}, {%4,%5,%6,%7}, {%8,%9}, {%0,%1,%2,%3};"
                 : "+f"(d[0]), "+f"(d[1]), "+f"(d[2]), "+f"(d[3])
                 : "r"(a[0]), "r"(a[1]), "r"(a[2]), "r"(a[3]), "r"(b0), "r"(b1));
}

// =====================================================================
// K1: Wh = x @ W (fp32 f32x2) + FUSED attention-vector epilogue
// =====================================================================
__global__ __launch_bounds__(256) void k_gemm_wh(const float* __restrict__ x,
                                                 const float* __restrict__ W,
                                                 const float* __restrict__ aw,
                                                 const float* __restrict__ ab) {
    __shared__ __align__(16) float Xs[64][32];
    __shared__ __align__(16) float Ws[32][256];
    const int r0 = blockIdx.x * 64;
    const int tid = threadIdx.x, lane = tid & 31, w = tid >> 5;

    unsigned long long acc[8][4];
#pragma unroll
    for (int r = 0; r < 8; r++)
#pragma unroll
        for (int m = 0; m < 4; m++) acc[r][m] = 0ull;

    for (int k0 = 0; k0 < FD; k0 += 32) {
#pragma unroll
        for (int rr = 0; rr < 8; rr++) {
            int e = tid + 256 * rr;
            Xs[e >> 5][e & 31] = x[(r0 + (e >> 5)) * FD + k0 + (e & 31)];
        }
#pragma unroll
        for (int rr = 0; rr < 8; rr++) {
            int e = tid + 256 * rr;
            int j = e >> 6, o4 = e & 63;
            *(float4*)&Ws[j][o4 * 4] = *(const float4*)&W[(k0 + j) * FD + o4 * 4];
        }
        __syncthreads();
#pragma unroll 4
        for (int kk = 0; kk < 32; kk++) {
            unsigned long long cb[8];
#pragma unroll
            for (int r = 0; r < 8; r++) { float c = Xs[8 * w + r][kk]; cb[r] = pack2(c, c); }
            unsigned long long wv[4];
#pragma unroll
            for (int m = 0; m < 4; m++)
                wv[m] = *(const unsigned long long*)&Ws[kk][2 * lane + 64 * m];
#pragma unroll
            for (int r = 0; r < 8; r++)
#pragma unroll
                for (int m = 0; m < 4; m++) ffma2(acc[r][m], cb[r], wv[m]);
        }
        __syncthreads();
    }

    float2 a1v[4], a2v[4];
#pragma unroll
    for (int m = 0; m < 4; m++) {
        a1v[m] = *(const float2*)&aw[2 * lane + 64 * m];
        a2v[m] = *(const float2*)&aw[FD + 2 * lane + 64 * m];
    }
#pragma unroll
    for (int r = 0; r < 8; r++) {
        float s1 = 0.f, s2 = 0.f;
#pragma unroll
        for (int m = 0; m < 4; m++) {
            float2 v = unpack2(acc[r][m]);
            *(float2*)&g_Wh[(r0 + 8 * w + r) * FD + 2 * lane + 64 * m] = v;
            s1 += v.x * a1v[m].x + v.y * a1v[m].y;
            s2 += v.x * a2v[m].x + v.y * a2v[m].y;
        }
#pragma unroll
        for (int off = 16; off > 0; off >>= 1) {
            s1 += __shfl_xor_sync(0xffffffffu, s1, off);
            s2 += __shfl_xor_sync(0xffffffffu, s2, off);
        }
        if (lane == 0) {
            int row = r0 + 8 * w + r;
            float P = s1, Q = s2 + ab[0];
            g_P[row] = P; g_Q[row] = Q;
            g_E1[row] = expf(P);          g_E2[row] = expf(NSLOPE * P);
            g_F1[row] = expf(Q);          g_F2[row] = expf(NSLOPE * Q);
            g_D[row] = 0.f;
        }
    }
}

// =====================================================================
// K3: column sums D[b,j] + E-folded fp16 masks, 2 j per thread,
// default cache ops (NO ldcs/stcs — masks must stay in L2 for k_mma).
// grid: (NN/512, BATCH, NN/256), 256 threads
// =====================================================================
__global__ __launch_bounds__(256) void k_colsum(const float* __restrict__ A) {
    const int b = blockIdx.y;
    const int j0 = blockIdx.x * 512 + threadIdx.x * 2;
    const int ibase = blockIdx.z * 256;
    __shared__ float sP[256], sE1[256], sE2[256];
    __shared__ __half sH1[256], sH2[256];
    {
        float e1 = g_E1[b * NN + ibase + threadIdx.x];
        float e2 = g_E2[b * NN + ibase + threadIdx.x];
        sP [threadIdx.x] = g_P[b * NN + ibase + threadIdx.x];
        sE1[threadIdx.x] = e1;  sE2[threadIdx.x] = e2;
        sH1[threadIdx.x] = __float2half_rn(e1);
        sH2[threadIdx.x] = __float2half_rn(e2);
    }
    __syncthreads();
    const float Qa = g_Q[b * NN + j0],     F1a = g_F1[b * NN + j0],
                F2a = g_F2[b * NN + j0];
    const float Qb = g_Q[b * NN + j0 + 1], F1b = g_F1[b * NN + j0 + 1],
                F2b = g_F2[b * NN + j0 + 1];
    const float* Ab = A + (size_t)(b * NN + ibase) * NN + j0;
    const __half hz = __ushort_as_half(0);
    float acc0 = 0.f, acc1 = 0.f;
#pragma unroll 4
    for (int ii = 0; ii < 256; ii++) {
        float2 a = *(const float2*)(Ab + (size_t)ii * NN);
        float p = sP[ii], e1 = sE1[ii], e2 = sE2[ii];
        bool pos0 = (p + Qa > 0.f), nz0 = (a.x != 0.f);
        bool pos1 = (p + Qb > 0.f), nz1 = (a.y != 0.f);
        acc0 = fmaf(a.x, pos0 ? e1 * F1a : e2 * F2a, acc0);
        acc1 = fmaf(a.y, pos1 ? e1 * F1b : e2 * F2b, acc1);
        __half h1 = sH1[ii], h2 = sH2[ii];
        __half2 m1, m2;
        m1.x = (nz0 && pos0)  ? h1 : hz;  m1.y = (nz1 && pos1)  ? h1 : hz;
        m2.x = (nz0 && !pos0) ? h2 : hz;  m2.y = (nz1 && !pos1) ? h2 : hz;
        size_t mi = (size_t)(b * NN + ibase + ii) * NN + j0;
        *(__half2*)&g_M1[mi] = m1;
        *(__half2*)&g_M2[mi] = m2;
    }
    atomicAdd(&g_D[b * NN + j0], acc0);
    atomicAdd(&g_D[b * NN + j0 + 1], acc1);
}

// =====================================================================
// K_hprep: H1 = (F1/D)*Wh, H2 = (F2/D)*Wh in fp16
// =====================================================================
__global__ __launch_bounds__(256) void k_hprep() {
    int e4 = blockIdx.x * 256 + threadIdx.x;
    int row = e4 >> 6;
    float inv = 1.f / (g_D[row] + EPSV);
    float r1 = g_F1[row] * inv, r2 = g_F2[row] * inv;
    float4 w = ((const float4*)g_Wh)[e4];
    __half2* h1 = (__half2*)g_H1;
    __half2* h2 = (__half2*)g_H2;
    h1[e4 * 2]     = __floats2half2_rn(w.x * r1, w.y * r1);
    h1[e4 * 2 + 1] = __floats2half2_rn(w.z * r1, w.w * r1);
    h2[e4 * 2]     = __floats2half2_rn(w.x * r2, w.y * r2);
    h2[e4 * 2 + 1] = __floats2half2_rn(w.z * r2, w.w * r2);
}

// =====================================================================
// K4: HMMA mask-GEMM, E-folded single accumulator (R7-proven, unchanged).
// Block 128i x 64o, 256 threads, warp tile 32i x 32o.
// 3-stage cp.async pipeline (72 KB SMEM) -> 3 CTAs/SM.
// =====================================================================
#define STG_STRIDE 24576
#define NSTAGE 3

__device__ __forceinline__ uint32_t m_off(int i, int cq) {
    return (uint32_t)(((i >> 1) << 7) + (((((i & 1) << 2) | cq) ^ ((i >> 1) & 7)) << 4));
}
__device__ __forceinline__ uint32_t b_off(int j, int oc) {
    return (uint32_t)((j << 7) + (((oc ^ (j & 7))) << 4));
}

__global__ void __launch_bounds__(256, 3) k_mma(float* __restrict__ out) {
    extern __shared__ __align__(128) char smem[];
    const uint32_t sb = smem_u32(smem);
    const int tid = threadIdx.x, lane = tid & 31, wid = tid >> 5;
    const int b = blockIdx.z;
    const int i0 = blockIdx.x * 128;
    const int o0 = blockIdx.y * 64;
    const int isub = (wid & 3) * 32;
    const int ocb = (wid >> 2) * 4;

    float acc[2][4][4];
#pragma unroll
    for (int m = 0; m < 2; m++)
#pragma unroll
        for (int n = 0; n < 4; n++)
#pragma unroll
            for (int k = 0; k < 4; k++) acc[m][n][k] = 0.f;

    auto issue = [&](int t) {
        const int j0 = t * 32;
        uint32_t stg = sb + (t % NSTAGE) * STG_STRIDE;
#pragma unroll
        for (int r = 0; r < 4; r++) {
            int idx = tid + 256 * r;
            int tens = idx >> 9, rem = idx & 511;
            int i = rem >> 2, cq = rem & 3;
            const __half* src = (tens ? g_M2 : g_M1) +
                ((size_t)(b * NN + i0 + i) * NN + j0 + cq * 8);
            cp_async16(stg + tens * 8192 + m_off(i, cq), src);
        }
#pragma unroll
        for (int r = 0; r < 2; r++) {
            int idx = tid + 256 * r;
            int tens = idx >> 8, rem = idx & 255;
            int j = rem >> 3, oc = rem & 7;
            const __half* src = (tens ? g_H2 : g_H1) +
                ((size_t)(b * NN + j0 + j) * FD + o0 + oc * 8);
            cp_async16(stg + 16384 + tens * 4096 + b_off(j, oc), src);
        }
        CP_COMMIT();
    };

    issue(0); issue(1);

    for (int t = 0; t < 64; t++) {
        if (t < 63) { asm volatile("cp.async.wait_group 1;" ::: "memory"); }
        else        { asm volatile("cp.async.wait_group 0;" ::: "memory"); }
        __syncthreads();

        uint32_t stg = sb + (t % NSTAGE) * STG_STRIDE;
#pragma unroll
        for (int tens = 0; tens < 2; tens++) {
            uint32_t Bf[4][4];
            uint32_t bb = stg + 16384 + tens * 4096;
#pragma unroll
            for (int jb = 0; jb < 4; jb++) {
                int oblk = lane >> 3;
                int j = jb * 8 + (lane & 7);
                uint32_t addr = bb + b_off(j, ocb + oblk);
                ldsm_x4_t(Bf[jb][0], Bf[jb][1], Bf[jb][2], Bf[jb][3], addr);
            }
            uint32_t mb = stg + tens * 8192;
#pragma unroll
            for (int m = 0; m < 2; m++) {
#pragma unroll
                for (int kt = 0; kt < 2; kt++) {
                    int q = lane >> 3;
                    int i = isub + m * 16 + ((q & 1) << 3) + (lane & 7);
                    int cq = (kt << 1) + (q >> 1);
                    uint32_t a[4];
                    ldsm_x4(a[0], a[1], a[2], a[3], mb + m_off(i, cq));
#pragma unroll
                    for (int nt = 0; nt < 4; nt++)
                        mma16816(acc[m][nt], a, Bf[2 * kt][nt], Bf[2 * kt + 1][nt]);
                }
            }
        }
        if (t + 2 < 64) issue(t + 2);
    }

    const int gid = lane >> 2, t4 = lane & 3;
#pragma unroll
    for (int m = 0; m < 2; m++) {
        int r0 = i0 + isub + m * 16 + gid;
        int r1 = r0 + 8;
#pragma unroll
        for (int nt = 0; nt < 4; nt++) {
            int o = o0 + ocb * 8 + nt * 8 + 2 * t4;
            float2 v0, v1;
            v0.x = acc[m][nt][0]; v0.y = acc[m][nt][1];
            v1.x = acc[m][nt][2]; v1.y = acc[m][nt][3];
            *(float2*)&out[(size_t)(b * NN + r0) * FD + o] = v0;
            *(float2*)&out[(size_t)(b * NN + r1) * FD + o] = v1;
        }
    }
}

// =====================================================================
extern "C" void kernel_launch(void* const* d_in, const int* in_sizes, int n_in,
                              void* d_out, int out_size) {
    (void)in_sizes; (void)n_in; (void)out_size;
    const float* A  = (const float*)d_in[0];
    const float* x  = (const float*)d_in[1];
    const float* W  = (const float*)d_in[2];
    const float* aw = (const float*)d_in[3];
    const float* ab = (const float*)d_in[4];
    float* out = (float*)d_out;

    cudaFuncSetAttribute(k_mma, cudaFuncAttributeMaxDynamicSharedMemorySize,
                         NSTAGE * STG_STRIDE);

    k_gemm_wh<<<(BATCH * NN) / 64, 256>>>(x, W, aw, ab);
    k_colsum<<<dim3(NN / 512, BATCH, NN / 256), 256>>>(A);
    k_hprep<<<(BATCH * NN * FD) / 1024, 256>>>();
    k_mma<<<dim3(NN / 128, FD / 64, BATCH), 256, NSTAGE * STG_STRIDE>>>(out);
}

// round 9
// speedup vs baseline: 1.3290x; 1.0095x over previous
#include <cuda_runtime.h>
#include <cuda_fp16.h>
#include <cstdint>

#define BATCH 8
#define NN 2048
#define FD 256
#define EPSV 1e-7f
#define NSLOPE 0.2f

// ---------------- device scratch ----------------
static __device__ float g_Wh[BATCH * NN * FD];                 // 16 MB
static __device__ float g_P [BATCH * NN];
static __device__ float g_Q [BATCH * NN];
static __device__ float g_E1[BATCH * NN];
static __device__ float g_E2[BATCH * NN];
static __device__ float g_F1[BATCH * NN];
static __device__ float g_F2[BATCH * NN];
static __device__ float g_D [BATCH * NN];
static __device__ __half g_M1[(size_t)BATCH * NN * NN];        // 64 MB E1-folded pos-mask
static __device__ __half g_M2[(size_t)BATCH * NN * NN];        // 64 MB E2-folded neg-mask
static __device__ __half g_H1[BATCH * NN * FD];                // (F1/D)*Wh fp16
static __device__ __half g_H2[BATCH * NN * FD];                // (F2/D)*Wh fp16

// ---------------- helpers ----------------
__device__ __forceinline__ unsigned long long pack2(float x, float y) {
    unsigned long long r;
    asm("mov.b64 %0, {%1, %2};" : "=l"(r) : "f"(x), "f"(y));
    return r;
}
__device__ __forceinline__ float2 unpack2(unsigned long long v) {
    float2 r;
    asm("mov.b64 {%0, %1}, %2;" : "=f"(r.x), "=f"(r.y) : "l"(v));
    return r;
}
__device__ __forceinline__ void ffma2(unsigned long long& d,
                                      unsigned long long a,
                                      unsigned long long b) {
    asm("fma.rn.f32x2 %0, %1, %2, %3;" : "=l"(d) : "l"(a), "l"(b), "l"(d));
}
__device__ __forceinline__ uint32_t smem_u32(const void* p) {
    uint32_t a;
    asm("{ .reg .u64 t; cvta.to.shared.u64 t, %1; cvt.u32.u64 %0, t; }" : "=r"(a) : "l"(p));
    return a;
}
__device__ __forceinline__ void cp_async16(uint32_t dst, const void* src) {
    asm volatile("cp.async.cg.shared.global [%0], [%1], 16;" :: "r"(dst), "l"(src));
}
#define CP_COMMIT() asm volatile("cp.async.commit_group;" ::: "memory")

__device__ __forceinline__ void ldsm_x4(uint32_t& r0, uint32_t& r1, uint32_t& r2,
                                        uint32_t& r3, uint32_t addr) {
    asm volatile("ldmatrix.sync.aligned.m8n8.x4.shared.b16 {%0,%1,%2,%3}, [%4];"
                 : "=r"(r0), "=r"(r1), "=r"(r2), "=r"(r3) : "r"(addr));
}
__device__ __forceinline__ void ldsm_x4_t(uint32_t& r0, uint32_t& r1, uint32_t& r2,
                                          uint32_t& r3, uint32_t addr) {
    asm volatile("ldmatrix.sync.aligned.m8n8.x4.trans.shared.b16 {%0,%1,%2,%3}, [%4];"
                 : "=r"(r0), "=r"(r1), "=r"(r2), "=r"(r3) : "r"(addr));
}
__device__ __forceinline__ void mma16816(float* d, const uint32_t* a, uint32_t b0,
                                         uint32_t b1) {
    asm volatile("mma.sync.aligned.m16n8k16.row.col.f32.f16.f16.f32 "
                 "{%0,%1,%2,%3}, {%4,%5,%6,%7}, {%8,%9}, {%0,%1,%2,%3};"
                 : "+f"(d[0]), "+f"(d[1]), "+f"(d[2]), "+f"(d[3])
                 : "r"(a[0]), "r"(a[1]), "r"(a[2]), "r"(a[3]), "r"(b0), "r"(b1));
}

// =====================================================================
// K1: Wh = x @ W (fp32 f32x2) + FUSED attention-vector epilogue
// =====================================================================
__global__ __launch_bounds__(256) void k_gemm_wh(const float* __restrict__ x,
                                                 const float* __restrict__ W,
                                                 const float* __restrict__ aw,
                                                 const float* __restrict__ ab) {
    __shared__ __align__(16) float Xs[64][32];
    __shared__ __align__(16) float Ws[32][256];
    const int r0 = blockIdx.x * 64;
    const int tid = threadIdx.x, lane = tid & 31, w = tid >> 5;

    unsigned long long acc[8][4];
#pragma unroll
    for (int r = 0; r < 8; r++)
#pragma unroll
        for (int m = 0; m < 4; m++) acc[r][m] = 0ull;

    for (int k0 = 0; k0 < FD; k0 += 32) {
#pragma unroll
        for (int rr = 0; rr < 8; rr++) {
            int e = tid + 256 * rr;
            Xs[e >> 5][e & 31] = x[(r0 + (e >> 5)) * FD + k0 + (e & 31)];
        }
#pragma unroll
        for (int rr = 0; rr < 8; rr++) {
            int e = tid + 256 * rr;
            int j = e >> 6, o4 = e & 63;
            *(float4*)&Ws[j][o4 * 4] = *(const float4*)&W[(k0 + j) * FD + o4 * 4];
        }
        __syncthreads();
#pragma unroll 4
        for (int kk = 0; kk < 32; kk++) {
            unsigned long long cb[8];
#pragma unroll
            for (int r = 0; r < 8; r++) { float c = Xs[8 * w + r][kk]; cb[r] = pack2(c, c); }
            unsigned long long wv[4];
#pragma unroll
            for (int m = 0; m < 4; m++)
                wv[m] = *(const unsigned long long*)&Ws[kk][2 * lane + 64 * m];
#pragma unroll
            for (int r = 0; r < 8; r++)
#pragma unroll
                for (int m = 0; m < 4; m++) ffma2(acc[r][m], cb[r], wv[m]);
        }
        __syncthreads();
    }

    float2 a1v[4], a2v[4];
#pragma unroll
    for (int m = 0; m < 4; m++) {
        a1v[m] = *(const float2*)&aw[2 * lane + 64 * m];
        a2v[m] = *(const float2*)&aw[FD + 2 * lane + 64 * m];
    }
#pragma unroll
    for (int r = 0; r < 8; r++) {
        float s1 = 0.f, s2 = 0.f;
#pragma unroll
        for (int m = 0; m < 4; m++) {
            float2 v = unpack2(acc[r][m]);
            *(float2*)&g_Wh[(r0 + 8 * w + r) * FD + 2 * lane + 64 * m] = v;
            s1 += v.x * a1v[m].x + v.y * a1v[m].y;
            s2 += v.x * a2v[m].x + v.y * a2v[m].y;
        }
#pragma unroll
        for (int off = 16; off > 0; off >>= 1) {
            s1 += __shfl_xor_sync(0xffffffffu, s1, off);
            s2 += __shfl_xor_sync(0xffffffffu, s2, off);
        }
        if (lane == 0) {
            int row = r0 + 8 * w + r;
            float P = s1, Q = s2 + ab[0];
            g_P[row] = P; g_Q[row] = Q;
            g_E1[row] = expf(P);          g_E2[row] = expf(NSLOPE * P);
            g_F1[row] = expf(Q);          g_F2[row] = expf(NSLOPE * Q);
            g_D[row] = 0.f;
        }
    }
}

// =====================================================================
// K3: column sums D[b,j] + E-folded fp16 masks, 2 j per thread
// =====================================================================
__global__ __launch_bounds__(256) void k_colsum(const float* __restrict__ A) {
    const int b = blockIdx.y;
    const int j0 = blockIdx.x * 512 + threadIdx.x * 2;
    const int ibase = blockIdx.z * 256;
    __shared__ float sP[256], sE1[256], sE2[256];
    __shared__ __half sH1[256], sH2[256];
    {
        float e1 = g_E1[b * NN + ibase + threadIdx.x];
        float e2 = g_E2[b * NN + ibase + threadIdx.x];
        sP [threadIdx.x] = g_P[b * NN + ibase + threadIdx.x];
        sE1[threadIdx.x] = e1;  sE2[threadIdx.x] = e2;
        sH1[threadIdx.x] = __float2half_rn(e1);
        sH2[threadIdx.x] = __float2half_rn(e2);
    }
    __syncthreads();
    const float Qa = g_Q[b * NN + j0],     F1a = g_F1[b * NN + j0],
                F2a = g_F2[b * NN + j0];
    const float Qb = g_Q[b * NN + j0 + 1], F1b = g_F1[b * NN + j0 + 1],
                F2b = g_F2[b * NN + j0 + 1];
    const float* Ab = A + (size_t)(b * NN + ibase) * NN + j0;
    const __half hz = __ushort_as_half(0);
    float acc0 = 0.f, acc1 = 0.f;
#pragma unroll 4
    for (int ii = 0; ii < 256; ii++) {
        float2 a = *(const float2*)(Ab + (size_t)ii * NN);
        float p = sP[ii], e1 = sE1[ii], e2 = sE2[ii];
        bool pos0 = (p + Qa > 0.f), nz0 = (a.x != 0.f);
        bool pos1 = (p + Qb > 0.f), nz1 = (a.y != 0.f);
        acc0 = fmaf(a.x, pos0 ? e1 * F1a : e2 * F2a, acc0);
        acc1 = fmaf(a.y, pos1 ? e1 * F1b : e2 * F2b, acc1);
        __half h1 = sH1[ii], h2 = sH2[ii];
        __half2 m1, m2;
        m1.x = (nz0 && pos0)  ? h1 : hz;  m1.y = (nz1 && pos1)  ? h1 : hz;
        m2.x = (nz0 && !pos0) ? h2 : hz;  m2.y = (nz1 && !pos1) ? h2 : hz;
        size_t mi = (size_t)(b * NN + ibase + ii) * NN + j0;
        *(__half2*)&g_M1[mi] = m1;
        *(__half2*)&g_M2[mi] = m2;
    }
    atomicAdd(&g_D[b * NN + j0], acc0);
    atomicAdd(&g_D[b * NN + j0 + 1], acc1);
}

// =====================================================================
// K_hprep: H1 = (F1/D)*Wh, H2 = (F2/D)*Wh in fp16
// =====================================================================
__global__ __launch_bounds__(256) void k_hprep() {
    int e4 = blockIdx.x * 256 + threadIdx.x;
    int row = e4 >> 6;
    float inv = 1.f / (g_D[row] + EPSV);
    float r1 = g_F1[row] * inv, r2 = g_F2[row] * inv;
    float4 w = ((const float4*)g_Wh)[e4];
    __half2* h1 = (__half2*)g_H1;
    __half2* h2 = (__half2*)g_H2;
    h1[e4 * 2]     = __floats2half2_rn(w.x * r1, w.y * r1);
    h1[e4 * 2 + 1] = __floats2half2_rn(w.z * r1, w.w * r1);
    h2[e4 * 2]     = __floats2half2_rn(w.x * r2, w.y * r2);
    h2[e4 * 2 + 1] = __floats2half2_rn(w.z * r2, w.w * r2);
}

// =====================================================================
// K4: HMMA mask-GEMM, E-folded. 128 threads = 4 warps of 64i x 32o
// (B-fragment reuse m=4 -> LDS bytes/HMMA cut from 384 to 256).
// Block 128i x 64o; 3-stage cp.async pipeline (72 KB) -> 3 CTAs/SM.
// Stage SMEM (24576B): M1 8K | M2 8K | B1 4K | B2 4K.
// =====================================================================
#define STG_STRIDE 24576
#define NSTAGE 3

__device__ __forceinline__ uint32_t m_off(int i, int cq) {
    return (uint32_t)(((i >> 1) << 7) + (((((i & 1) << 2) | cq) ^ ((i >> 1) & 7)) << 4));
}
__device__ __forceinline__ uint32_t b_off(int j, int oc) {
    return (uint32_t)((j << 7) + (((oc ^ (j & 7))) << 4));
}

__global__ void __launch_bounds__(128, 3) k_mma(float* __restrict__ out) {
    extern __shared__ __align__(128) char smem[];
    const uint32_t sb = smem_u32(smem);
    const int tid = threadIdx.x, lane = tid & 31, wid = tid >> 5;
    const int b = blockIdx.z;
    const int i0 = blockIdx.x * 128;
    const int o0 = blockIdx.y * 64;
    const int isub = (wid & 1) * 64;       // warp's 64-i subtile
    const int ocb  = (wid >> 1) * 4;       // warp's 32-o subtile (4 chunks of 8)

    float acc[4][4][4];
#pragma unroll
    for (int m = 0; m < 4; m++)
#pragma unroll
        for (int n = 0; n < 4; n++)
#pragma unroll
            for (int k = 0; k < 4; k++) acc[m][n][k] = 0.f;

    auto issue = [&](int t) {
        const int j0 = t * 32;
        uint32_t stg = sb + (t % NSTAGE) * STG_STRIDE;
#pragma unroll
        for (int r = 0; r < 8; r++) {
            int idx = tid + 128 * r;
            int tens = idx >> 9, rem = idx & 511;
            int i = rem >> 2, cq = rem & 3;
            const __half* src = (tens ? g_M2 : g_M1) +
                ((size_t)(b * NN + i0 + i) * NN + j0 + cq * 8);
            cp_async16(stg + tens * 8192 + m_off(i, cq), src);
        }
#pragma unroll
        for (int r = 0; r < 4; r++) {
            int idx = tid + 128 * r;
            int tens = idx >> 8, rem = idx & 255;
            int j = rem >> 3, oc = rem & 7;
            const __half* src = (tens ? g_H2 : g_H1) +
                ((size_t)(b * NN + j0 + j) * FD + o0 + oc * 8);
            cp_async16(stg + 16384 + tens * 4096 + b_off(j, oc), src);
        }
        CP_COMMIT();
    };

    issue(0); issue(1);

    for (int t = 0; t < 64; t++) {
        if (t < 63) { asm volatile("cp.async.wait_group 1;" ::: "memory"); }
        else        { asm volatile("cp.async.wait_group 0;" ::: "memory"); }
        __syncthreads();

        uint32_t stg = sb + (t % NSTAGE) * STG_STRIDE;
#pragma unroll
        for (int tens = 0; tens < 2; tens++) {
            uint32_t Bf[4][4];
            uint32_t bb = stg + 16384 + tens * 4096;
#pragma unroll
            for (int jb = 0; jb < 4; jb++) {
                int oblk = lane >> 3;
                int j = jb * 8 + (lane & 7);
                uint32_t addr = bb + b_off(j, ocb + oblk);
                ldsm_x4_t(Bf[jb][0], Bf[jb][1], Bf[jb][2], Bf[jb][3], addr);
            }
            uint32_t mb = stg + tens * 8192;
#pragma unroll
            for (int m = 0; m < 4; m++) {
#pragma unroll
                for (int kt = 0; kt < 2; kt++) {
                    int q = lane >> 3;
                    int i = isub + m * 16 + ((q & 1) << 3) + (lane & 7);
                    int cq = (kt << 1) + (q >> 1);
                    uint32_t a[4];
                    ldsm_x4(a[0], a[1], a[2], a[3], mb + m_off(i, cq));
#pragma unroll
                    for (int nt = 0; nt < 4; nt++)
                        mma16816(acc[m][nt], a, Bf[2 * kt][nt], Bf[2 * kt + 1][nt]);
                }
            }
        }
        if (t + 2 < 64) issue(t + 2);
    }

    const int gid = lane >> 2, t4 = lane & 3;
#pragma unroll
    for (int m = 0; m < 4; m++) {
        int r0 = i0 + isub + m * 16 + gid;
        int r1 = r0 + 8;
#pragma unroll
        for (int nt = 0; nt < 4; nt++) {
            int o = o0 + ocb * 8 + nt * 8 + 2 * t4;
            float2 v0, v1;
            v0.x = acc[m][nt][0]; v0.y = acc[m][nt][1];
            v1.x = acc[m][nt][2]; v1.y = acc[m][nt][3];
            *(float2*)&out[(size_t)(b * NN + r0) * FD + o] = v0;
            *(float2*)&out[(size_t)(b * NN + r1) * FD + o] = v1;
        }
    }
}

// =====================================================================
extern "C" void kernel_launch(void* const* d_in, const int* in_sizes, int n_in,
                              void* d_out, int out_size) {
    (void)in_sizes; (void)n_in; (void)out_size;
    const float* A  = (const float*)d_in[0];
    const float* x  = (const float*)d_in[1];
    const float* W  = (const float*)d_in[2];
    const float* aw = (const float*)d_in[3];
    const float* ab = (const float*)d_in[4];
    float* out = (float*)d_out;

    cudaFuncSetAttribute(k_mma, cudaFuncAttributeMaxDynamicSharedMemorySize,
                         NSTAGE * STG_STRIDE);

    k_gemm_wh<<<(BATCH * NN) / 64, 256>>>(x, W, aw, ab);
    k_colsum<<<dim3(NN / 512, BATCH, NN / 256), 256>>>(A);
    k_hprep<<<(BATCH * NN * FD) / 1024, 256>>>();
    k_mma<<<dim3(NN / 128, FD / 64, BATCH), 128, NSTAGE * STG_STRIDE>>>(out);
}